// round 7
// baseline (speedup 1.0000x reference)
#include <cuda_runtime.h>
#include <math.h>
#include <stdint.h>

#define Nn 4096
#define Dd 512
#define D3 1536
#define Ee 131072
#define MAXNB 128
#define HEADS 8
#define HD 64

// ---------------- scratch (device globals; referenced ONLY from device code) ----------------
__device__ int   g_winner[Nn * Nn];     // 0 = empty; else edge_id+1 (zero-init, self-restoring)
__device__ __align__(128) int   g_cnt[Nn];
__device__ __align__(128) int   g_cols[Nn * MAXNB];
__device__ __align__(128) float g_wts[Nn * MAXNB];
__device__ __align__(128) float g_qkv[Nn * D3];
__device__ __align__(128) float g_attn[Nn * Dd];
__device__ __align__(128) float g_tmp[Nn * Dd];
__device__ __align__(128) float g_h1[Nn * Dd];

// ---------------- helpers ----------------
__device__ __forceinline__ uint32_t smem_u32(const void* p) {
    uint32_t a;
    asm("{ .reg .u64 t; cvta.to.shared.u64 t, %1; cvt.u32.u64 %0, t; }" : "=r"(a) : "l"(p));
    return a;
}
__device__ __forceinline__ uint32_t f2tf(float f) {
    uint32_t u;
    asm("cvt.rna.tf32.f32 %0, %1;" : "=r"(u) : "f"(f));
    return u;
}
__device__ __forceinline__ void cp16(uint32_t dst, const void* src) {
    asm volatile("cp.async.ca.shared.global [%0], [%1], 16;" :: "r"(dst), "l"(src));
}
__device__ __forceinline__ void mma8(float* c, const uint32_t* a, const uint32_t* b) {
    asm volatile(
        "mma.sync.aligned.m16n8k8.row.col.f32.tf32.tf32.f32 "
        "{%0,%1,%2,%3},{%4,%5,%6,%7},{%8,%9},{%0,%1,%2,%3};"
        : "+f"(c[0]), "+f"(c[1]), "+f"(c[2]), "+f"(c[3])
        : "r"(a[0]), "r"(a[1]), "r"(a[2]), "r"(a[3]), "r"(b[0]), "r"(b[1]));
}

// ---------------- edge access (dtype auto-detect per-thread) ----------------
__device__ __forceinline__ bool edge_is64(const void* ei) {
    const uint32_t* w = (const uint32_t*)ei;
    return (w[1] | w[3] | w[5] | w[7]) == 0u;
}
__device__ __forceinline__ int2 load_edge(const void* ei, int e, bool is64) {
    int2 r;
    if (is64) {
        const long long* p = (const long long*)ei;
        r.x = (int)p[e];
        r.y = (int)p[Ee + e];
    } else {
        const int* p = (const int*)ei;
        r.x = p[e];
        r.y = p[Ee + e];
    }
    return r;
}

// ---------------- adjacency build ----------------
__global__ void k_scatter(const void* __restrict__ ei) {
    int e = blockIdx.x * blockDim.x + threadIdx.x;
    if (e < Nn) g_cnt[e] = 0;
    if (e >= Ee) return;
    bool is64 = edge_is64(ei);
    int2 sd = load_edge(ei, e, is64);
    if ((unsigned)sd.x >= Nn || (unsigned)sd.y >= Nn) return;
    atomicMax(&g_winner[sd.y * Nn + sd.x], e + 1);
}

__global__ void k_append(const void* __restrict__ ei, const float* __restrict__ ew) {
    int e = blockIdx.x * blockDim.x + threadIdx.x;
    if (e < Nn && g_winner[e * Nn + e] == 0) {       // self edge (diag not overridden)
        int s = atomicAdd(&g_cnt[e], 1);
        if (s < MAXNB) { g_cols[e * MAXNB + s] = e; g_wts[e * MAXNB + s] = 0.0f; }
    }
    if (e >= Ee) return;
    bool is64 = edge_is64(ei);
    int2 sd = load_edge(ei, e, is64);
    if ((unsigned)sd.x >= Nn || (unsigned)sd.y >= Nn) return;
    if (g_winner[sd.y * Nn + sd.x] == e + 1) {       // surviving write for (dst,src)
        int s = atomicAdd(&g_cnt[sd.y], 1);
        if (s < MAXNB) { g_cols[sd.y * MAXNB + s] = sd.x; g_wts[sd.y * MAXNB + s] = ew[e]; }
    }
}

__global__ void k_cleanup(const void* __restrict__ ei) {
    int e = blockIdx.x * blockDim.x + threadIdx.x;
    if (e >= Ee) return;
    bool is64 = edge_is64(ei);
    int2 sd = load_edge(ei, e, is64);
    if ((unsigned)sd.x >= Nn || (unsigned)sd.y >= Nn) return;
    g_winner[sd.y * Nn + sd.x] = 0;                  // restore zero-state for next replay
}

// ---------------- tf32 mma GEMM: C[M,N] = A[M,K] * B[N,K]^T + bias[N] ----------------
// 128x128 CTA tile, 4 warps of 64x64, K-slab 16, cp.async double-buffered smem.
#define BM 128
#define BN 128
#define SLAB 16
#define NSLAB (Dd / SLAB)   // 32
#define SPAD 20             // conflict-free fragment loads

template<int MODE>
__global__ __launch_bounds__(128) void tc_gemm(
    const float* __restrict__ Ax,
    const float* __restrict__ Bw,
    const float* __restrict__ bias)
{
    constexpr int N = (MODE == 0) ? D3 : Dd;
    constexpr int K = Dd;
    const float* A = (MODE == 0) ? Ax : ((MODE == 1) ? (const float*)g_attn : (const float*)g_h1);
    float*       C = (MODE == 0) ? (float*)g_qkv : (float*)g_tmp;

    __shared__ float As[2][BM * SPAD];
    __shared__ float Bs[2][BN * SPAD];

    int tid  = threadIdx.x;
    int warp = tid >> 5;
    int lane = tid & 31;
    int g  = lane >> 2;              // 0..7
    int t4 = lane & 3;               // 0..3
    int wRow = (warp >> 1) * 64;     // 0 or 64
    int wCol = (warp & 1) * 64;      // 0 or 64

    int rowBase = blockIdx.y * BM;
    int colBase = blockIdx.x * BN;

    const float* Ag = A  + (size_t)(rowBase + tid) * K;   // one row per thread
    const float* Bg = Bw + (size_t)(colBase + tid) * K;
    uint32_t dA[2], dB[2];
    dA[0] = smem_u32(&As[0][tid * SPAD]);
    dA[1] = smem_u32(&As[1][tid * SPAD]);
    dB[0] = smem_u32(&Bs[0][tid * SPAD]);
    dB[1] = smem_u32(&Bs[1][tid * SPAD]);

    float acc[4][8][4];
    #pragma unroll
    for (int mt = 0; mt < 4; mt++)
        #pragma unroll
        for (int nt = 0; nt < 8; nt++)
            #pragma unroll
            for (int j = 0; j < 4; j++) acc[mt][nt][j] = 0.0f;

    // prologue: stage slab 0 into buffer 0
    #pragma unroll
    for (int c = 0; c < 4; c++) {
        cp16(dA[0] + c * 16, Ag + c * 4);
        cp16(dB[0] + c * 16, Bg + c * 4);
    }
    asm volatile("cp.async.commit_group;" ::: "memory");

    for (int s = 0; s < NSLAB; s++) {
        int b = s & 1;
        if (s + 1 < NSLAB) {
            const float* a2 = Ag + (s + 1) * SLAB;
            const float* b2 = Bg + (s + 1) * SLAB;
            #pragma unroll
            for (int c = 0; c < 4; c++) {
                cp16(dA[b ^ 1] + c * 16, a2 + c * 4);
                cp16(dB[b ^ 1] + c * 16, b2 + c * 4);
            }
        }
        asm volatile("cp.async.commit_group;" ::: "memory");
        asm volatile("cp.async.wait_group 1;" ::: "memory");
        __syncthreads();

        #pragma unroll
        for (int ks = 0; ks < SLAB; ks += 8) {
            uint32_t ua[4][4], ub[8][2];
            #pragma unroll
            for (int mt = 0; mt < 4; mt++) {
                int r0 = wRow + mt * 16 + g;
                ua[mt][0] = f2tf(As[b][(r0)     * SPAD + ks + t4]);
                ua[mt][1] = f2tf(As[b][(r0 + 8) * SPAD + ks + t4]);
                ua[mt][2] = f2tf(As[b][(r0)     * SPAD + ks + t4 + 4]);
                ua[mt][3] = f2tf(As[b][(r0 + 8) * SPAD + ks + t4 + 4]);
            }
            #pragma unroll
            for (int nt = 0; nt < 8; nt++) {
                int c0 = wCol + nt * 8 + g;
                ub[nt][0] = f2tf(Bs[b][c0 * SPAD + ks + t4]);
                ub[nt][1] = f2tf(Bs[b][c0 * SPAD + ks + t4 + 4]);
            }
            #pragma unroll
            for (int mt = 0; mt < 4; mt++)
                #pragma unroll
                for (int nt = 0; nt < 8; nt++)
                    mma8(acc[mt][nt], ua[mt], ub[nt]);
        }
        __syncthreads();
    }

    // epilogue: c0,c1 -> (row g, col 2*t4..+1); c2,c3 -> row g+8
    #pragma unroll
    for (int mt = 0; mt < 4; mt++) {
        #pragma unroll
        for (int nt = 0; nt < 8; nt++) {
            float* cf = acc[mt][nt];
            int r  = rowBase + wRow + mt * 16 + g;
            int cc = colBase + wCol + nt * 8 + t4 * 2;
            float bx = bias[cc], by = bias[cc + 1];
            *(float2*)(C + (size_t)r * N + cc)       = make_float2(cf[0] + bx, cf[1] + by);
            *(float2*)(C + (size_t)(r + 8) * N + cc) = make_float2(cf[2] + bx, cf[3] + by);
        }
    }
}

// ---------------- sparse attention: one block per query row, one warp per head ----------------
__global__ __launch_bounds__(256) void sparse_attn() {
    int i = blockIdx.x;
    int h = threadIdx.x >> 5;
    int lane = threadIdx.x & 31;
    int cnt = g_cnt[i];
    if (cnt > MAXNB) cnt = MAXNB;

    __shared__ float sc[HEADS][MAXNB];
    __shared__ int   cols_s[MAXNB];
    __shared__ float wts_s[MAXNB];

    for (int t = threadIdx.x; t < cnt; t += 256) {
        cols_s[t] = g_cols[i * MAXNB + t];
        wts_s[t]  = g_wts[i * MAXNB + t];
    }
    __syncthreads();

    float2 qv = *(const float2*)(g_qkv + (size_t)i * D3 + h * HD + lane * 2);

    for (int t = 0; t < cnt; t++) {
        int j = cols_s[t];
        float2 kv = *(const float2*)(g_qkv + (size_t)j * D3 + Dd + h * HD + lane * 2);
        float d = qv.x * kv.x + qv.y * kv.y;
        #pragma unroll
        for (int o = 16; o; o >>= 1) d += __shfl_xor_sync(0xffffffffu, d, o);
        if (lane == 0) sc[h][t] = d * 0.125f + wts_s[t];
    }
    __syncwarp();

    float m = -1e30f;
    for (int t = lane; t < cnt; t += 32) m = fmaxf(m, sc[h][t]);
    #pragma unroll
    for (int o = 16; o; o >>= 1) m = fmaxf(m, __shfl_xor_sync(0xffffffffu, m, o));

    float s = 0.0f;
    for (int t = lane; t < cnt; t += 32) {
        float e = expf(sc[h][t] - m);
        sc[h][t] = e;
        s += e;
    }
    #pragma unroll
    for (int o = 16; o; o >>= 1) s += __shfl_xor_sync(0xffffffffu, s, o);
    float inv = 1.0f / s;
    __syncwarp();

    float2 acc = make_float2(0.0f, 0.0f);
    for (int t = 0; t < cnt; t++) {
        float p = sc[h][t] * inv;
        int j = cols_s[t];
        float2 vv = *(const float2*)(g_qkv + (size_t)j * D3 + 2 * Dd + h * HD + lane * 2);
        acc.x += p * vv.x;
        acc.y += p * vv.y;
    }
    float* op = g_attn + (size_t)i * Dd + h * HD + lane * 2;
    op[0] = acc.x;
    op[1] = acc.y;
}

// ---------------- add + LayerNorm ----------------
// MODE 0: g_h1 = LN(x_arg + g_tmp);  MODE 1: out_ext = LN(g_h1 + g_tmp)
template<int MODE>
__global__ __launch_bounds__(256) void add_ln(
    const float* __restrict__ a_in,
    const float* __restrict__ g, const float* __restrict__ be,
    float* __restrict__ out_ext)
{
    const float* a = (MODE == 0) ? a_in : (const float*)g_h1;
    const float* b = (const float*)g_tmp;
    float*       o = (MODE == 0) ? (float*)g_h1 : out_ext;

    int i = blockIdx.x;
    int t = threadIdx.x;
    int lane = t & 31, w = t >> 5;
    __shared__ float sh[8];

    float2 av = *(const float2*)(a + (size_t)i * Dd + t * 2);
    float2 bv = *(const float2*)(b + (size_t)i * Dd + t * 2);
    float yx = av.x + bv.x;
    float yy = av.y + bv.y;

    float s = yx + yy;
    #pragma unroll
    for (int oo = 16; oo; oo >>= 1) s += __shfl_xor_sync(0xffffffffu, s, oo);
    if (lane == 0) sh[w] = s;
    __syncthreads();
    if (t == 0) {
        float tot = 0;
        #pragma unroll
        for (int k = 0; k < 8; k++) tot += sh[k];
        sh[0] = tot;
    }
    __syncthreads();
    float mu = sh[0] * (1.0f / Dd);
    __syncthreads();

    float dx = yx - mu, dy = yy - mu;
    float qq = dx * dx + dy * dy;
    #pragma unroll
    for (int oo = 16; oo; oo >>= 1) qq += __shfl_xor_sync(0xffffffffu, qq, oo);
    if (lane == 0) sh[w] = qq;
    __syncthreads();
    if (t == 0) {
        float tot = 0;
        #pragma unroll
        for (int k = 0; k < 8; k++) tot += sh[k];
        sh[0] = tot;
    }
    __syncthreads();
    float var = sh[0] * (1.0f / Dd);
    float r = rsqrtf(var + 1e-5f);

    float2 gv  = *(const float2*)(g + t * 2);
    float2 bev = *(const float2*)(be + t * 2);
    float2 o2;
    o2.x = dx * r * gv.x + bev.x;
    o2.y = dy * r * gv.y + bev.y;
    *(float2*)(o + (size_t)i * Dd + t * 2) = o2;
}

// ---------------- launch ----------------
extern "C" void kernel_launch(void* const* d_in, const int* in_sizes, int n_in,
                              void* d_out, int out_size) {
    const float* x    = (const float*)d_in[0];
    const void*  ei   = d_in[1];
    const float* ew   = (const float*)d_in[2];
    const float* Wqkv = (const float*)d_in[3];
    const float* bqkv = (const float*)d_in[4];
    const float* Wo   = (const float*)d_in[5];
    const float* bo   = (const float*)d_in[6];
    const float* W1   = (const float*)d_in[7];
    const float* b1   = (const float*)d_in[8];
    const float* g1   = (const float*)d_in[9];
    const float* be1  = (const float*)d_in[10];
    const float* g2   = (const float*)d_in[11];
    const float* be2  = (const float*)d_in[12];
    float* out = (float*)d_out;

    // adjacency with exact last-write-wins dedup (winner grid self-restores to zero)
    k_scatter<<<Ee / 256, 256>>>(ei);
    k_append<<<Ee / 256, 256>>>(ei, ew);
    k_cleanup<<<Ee / 256, 256>>>(ei);

    // qkv = x @ Wqkv^T + bqkv            -> g_qkv
    tc_gemm<0><<<dim3(D3 / BN, Nn / BM), 128>>>(x, Wqkv, bqkv);

    // sparse multi-head attention        -> g_attn
    sparse_attn<<<Nn, 256>>>();

    // attn_out = g_attn @ Wo^T + bo      -> g_tmp
    tc_gemm<1><<<dim3(Dd / BN, Nn / BM), 128>>>(nullptr, Wo, bo);

    // h1 = LN(x + g_tmp)                 -> g_h1
    add_ln<0><<<Nn, 256>>>(x, g1, be1, out);

    // ffn = g_h1 @ W1^T + b1             -> g_tmp
    tc_gemm<2><<<dim3(Dd / BN, Nn / BM), 128>>>(nullptr, W1, b1);

    // out = LN(g_h1 + g_tmp)             -> out
    add_ln<1><<<Nn, 256>>>(nullptr, g2, be2, out);
}

// round 8
// speedup vs baseline: 1.0850x; 1.0850x over previous
#include <cuda_runtime.h>
#include <math.h>
#include <stdint.h>

#define Nn 4096
#define Dd 512
#define D3 1536
#define Ee 131072
#define MAXNB 128
#define HEADS 8
#define HD 64

// ---------------- scratch (device globals; referenced ONLY from device code) ----------------
__device__ int   g_winner[Nn * Nn];     // 0 = empty; else edge_id+1 (zero-init, self-restoring)
__device__ __align__(128) int   g_cnt[Nn];
__device__ __align__(128) int   g_cols[Nn * MAXNB];
__device__ __align__(128) float g_wts[Nn * MAXNB];
__device__ __align__(128) float g_qkv[Nn * D3];
__device__ __align__(128) float g_attn[Nn * Dd];
__device__ __align__(128) float g_tmp[Nn * Dd];
__device__ __align__(128) float g_h1[Nn * Dd];

// ---------------- helpers ----------------
__device__ __forceinline__ uint32_t smem_u32(const void* p) {
    uint32_t a;
    asm("{ .reg .u64 t; cvta.to.shared.u64 t, %1; cvt.u32.u64 %0, t; }" : "=r"(a) : "l"(p));
    return a;
}
__device__ __forceinline__ uint32_t f2tf(uint32_t fb) {
    uint32_t u;
    asm("cvt.rna.tf32.f32 %0, %1;" : "=r"(u) : "f"(__uint_as_float(fb)));
    return u;
}
__device__ __forceinline__ void cp16cg(uint32_t dst, const void* src) {
    asm volatile("cp.async.cg.shared.global [%0], [%1], 16;" :: "r"(dst), "l"(src));
}
__device__ __forceinline__ void ldsm4(uint32_t* r, uint32_t addr) {
    asm volatile("ldmatrix.sync.aligned.m8n8.x4.shared.b16 {%0,%1,%2,%3}, [%4];"
        : "=r"(r[0]), "=r"(r[1]), "=r"(r[2]), "=r"(r[3]) : "r"(addr));
}
__device__ __forceinline__ void mma8(float* c, const uint32_t* a, const uint32_t* b) {
    asm volatile(
        "mma.sync.aligned.m16n8k8.row.col.f32.tf32.tf32.f32 "
        "{%0,%1,%2,%3},{%4,%5,%6,%7},{%8,%9},{%0,%1,%2,%3};"
        : "+f"(c[0]), "+f"(c[1]), "+f"(c[2]), "+f"(c[3])
        : "r"(a[0]), "r"(a[1]), "r"(a[2]), "r"(a[3]), "r"(b[0]), "r"(b[1]));
}

// ---------------- edge access (dtype auto-detect per-thread) ----------------
__device__ __forceinline__ bool edge_is64(const void* ei) {
    const uint32_t* w = (const uint32_t*)ei;
    return (w[1] | w[3] | w[5] | w[7]) == 0u;
}
__device__ __forceinline__ int2 load_edge(const void* ei, int e, bool is64) {
    int2 r;
    if (is64) {
        const long long* p = (const long long*)ei;
        r.x = (int)p[e];
        r.y = (int)p[Ee + e];
    } else {
        const int* p = (const int*)ei;
        r.x = p[e];
        r.y = p[Ee + e];
    }
    return r;
}

// ---------------- adjacency build ----------------
__global__ void k_scatter(const void* __restrict__ ei) {
    int e = blockIdx.x * blockDim.x + threadIdx.x;
    if (e < Nn) g_cnt[e] = 0;
    if (e >= Ee) return;
    bool is64 = edge_is64(ei);
    int2 sd = load_edge(ei, e, is64);
    if ((unsigned)sd.x >= Nn || (unsigned)sd.y >= Nn) return;
    atomicMax(&g_winner[sd.y * Nn + sd.x], e + 1);
}

__global__ void k_append(const void* __restrict__ ei, const float* __restrict__ ew) {
    int e = blockIdx.x * blockDim.x + threadIdx.x;
    if (e < Nn && g_winner[e * Nn + e] == 0) {       // self edge (diag not overridden)
        int s = atomicAdd(&g_cnt[e], 1);
        if (s < MAXNB) { g_cols[e * MAXNB + s] = e; g_wts[e * MAXNB + s] = 0.0f; }
    }
    if (e >= Ee) return;
    bool is64 = edge_is64(ei);
    int2 sd = load_edge(ei, e, is64);
    if ((unsigned)sd.x >= Nn || (unsigned)sd.y >= Nn) return;
    if (g_winner[sd.y * Nn + sd.x] == e + 1) {       // surviving write for (dst,src)
        int s = atomicAdd(&g_cnt[sd.y], 1);
        if (s < MAXNB) { g_cols[sd.y * MAXNB + s] = sd.x; g_wts[sd.y * MAXNB + s] = ew[e]; }
    }
}

__global__ void k_cleanup(const void* __restrict__ ei) {
    int e = blockIdx.x * blockDim.x + threadIdx.x;
    if (e >= Ee) return;
    bool is64 = edge_is64(ei);
    int2 sd = load_edge(ei, e, is64);
    if ((unsigned)sd.x >= Nn || (unsigned)sd.y >= Nn) return;
    g_winner[sd.y * Nn + sd.x] = 0;                  // restore zero-state for next replay
}

// ---------------- tf32 mma GEMM: C[M,N] = A[M,K] * B[N,K]^T + bias[N] ----------------
// 128x128 CTA tile, 4 warps of 64x64, K-slab 16, cp.async.cg double-buffer, ldmatrix frags.
#define BM 128
#define BN 128
#define SLAB 16
#define NSLAB (Dd / SLAB)   // 32
#define SPAD 20             // row stride in floats: 80B (16B-aligned, ldmatrix conflict-free)

template<int MODE>
__global__ __launch_bounds__(128) void tc_gemm(
    const float* __restrict__ Ax,
    const float* __restrict__ Bw,
    const float* __restrict__ bias)
{
    constexpr int N = (MODE == 0) ? D3 : Dd;
    constexpr int K = Dd;
    const float* A = (MODE == 0) ? Ax : ((MODE == 1) ? (const float*)g_attn : (const float*)g_h1);
    float*       C = (MODE == 0) ? (float*)g_qkv : (float*)g_tmp;

    __shared__ __align__(16) float As[2][BM * SPAD];
    __shared__ __align__(16) float Bs[2][BN * SPAD];

    int tid  = threadIdx.x;
    int warp = tid >> 5;
    int lane = tid & 31;
    int g  = lane >> 2;
    int t4 = lane & 3;
    int wRow = (warp >> 1) * 64;
    int wCol = (warp & 1) * 64;

    int rowBase = blockIdx.y * BM;
    int colBase = blockIdx.x * BN;

    const float* Ag = A  + (size_t)(rowBase + tid) * K;   // one row per thread
    const float* Bg = Bw + (size_t)(colBase + tid) * K;
    uint32_t dA[2], dB[2];
    dA[0] = smem_u32(&As[0][tid * SPAD]);
    dA[1] = smem_u32(&As[1][tid * SPAD]);
    dB[0] = smem_u32(&Bs[0][tid * SPAD]);
    dB[1] = smem_u32(&Bs[1][tid * SPAD]);

    // ldmatrix lane-address bases (byte addresses into buffer 0)
    // A tile mt at k-step ks: addr = aBase + buf + (mt*16*SPAD + ks)*4
    //   row = wRow + (lane&15), col-quad = (lane>>4)*4
    uint32_t aBase = smem_u32(&As[0][0]) +
        4u * ((wRow + (lane & 15)) * SPAD + ((lane >> 4) & 1) * 4);
    // B pair p (tiles 2p,2p+1): row = wCol + (lane&7) + ((lane>>4)&1)*8, col-quad = ((lane>>3)&1)*4
    uint32_t bBase = smem_u32(&Bs[0][0]) +
        4u * ((wCol + (lane & 7) + ((lane >> 4) & 1) * 8) * SPAD + ((lane >> 3) & 1) * 4);
    const uint32_t ABUF = BM * SPAD * 4;
    const uint32_t BBUF = BN * SPAD * 4;

    float acc[4][8][4];
    #pragma unroll
    for (int mt = 0; mt < 4; mt++)
        #pragma unroll
        for (int nt = 0; nt < 8; nt++)
            #pragma unroll
            for (int j = 0; j < 4; j++) acc[mt][nt][j] = 0.0f;

    // prologue: stage slab 0 into buffer 0
    #pragma unroll
    for (int c = 0; c < 4; c++) {
        cp16cg(dA[0] + c * 16, Ag + c * 4);
        cp16cg(dB[0] + c * 16, Bg + c * 4);
    }
    asm volatile("cp.async.commit_group;" ::: "memory");

    for (int s = 0; s < NSLAB; s++) {
        int b = s & 1;
        if (s + 1 < NSLAB) {
            const float* a2 = Ag + (s + 1) * SLAB;
            const float* b2 = Bg + (s + 1) * SLAB;
            #pragma unroll
            for (int c = 0; c < 4; c++) {
                cp16cg(dA[b ^ 1] + c * 16, a2 + c * 4);
                cp16cg(dB[b ^ 1] + c * 16, b2 + c * 4);
            }
        }
        asm volatile("cp.async.commit_group;" ::: "memory");
        asm volatile("cp.async.wait_group 1;" ::: "memory");
        __syncthreads();

        uint32_t abuf = b ? ABUF : 0u;
        uint32_t bbuf = b ? BBUF : 0u;

        #pragma unroll
        for (int ks = 0; ks < SLAB; ks += 8) {
            uint32_t ua[4][4], ub[4][4];
            #pragma unroll
            for (int mt = 0; mt < 4; mt++)
                ldsm4(ua[mt], aBase + abuf + 4u * (mt * 16 * SPAD + ks));
            #pragma unroll
            for (int p = 0; p < 4; p++)
                ldsm4(ub[p], bBase + bbuf + 4u * (p * 16 * SPAD + ks));
            // convert fp32 bits -> tf32 (rna) in registers
            #pragma unroll
            for (int mt = 0; mt < 4; mt++)
                #pragma unroll
                for (int j = 0; j < 4; j++) ua[mt][j] = f2tf(ua[mt][j]);
            #pragma unroll
            for (int p = 0; p < 4; p++)
                #pragma unroll
                for (int j = 0; j < 4; j++) ub[p][j] = f2tf(ub[p][j]);

            #pragma unroll
            for (int mt = 0; mt < 4; mt++) {
                #pragma unroll
                for (int p = 0; p < 4; p++) {
                    mma8(acc[mt][2 * p],     ua[mt], &ub[p][0]);   // tile 2p   : regs 0,1
                    mma8(acc[mt][2 * p + 1], ua[mt], &ub[p][2]);   // tile 2p+1 : regs 2,3
                }
            }
        }
        __syncthreads();
    }

    // epilogue: c0,c1 -> (row g, col 2*t4..+1); c2,c3 -> row g+8
    #pragma unroll
    for (int mt = 0; mt < 4; mt++) {
        #pragma unroll
        for (int nt = 0; nt < 8; nt++) {
            float* cf = acc[mt][nt];
            int r  = rowBase + wRow + mt * 16 + g;
            int cc = colBase + wCol + nt * 8 + t4 * 2;
            float bx = bias[cc], by = bias[cc + 1];
            *(float2*)(C + (size_t)r * N + cc)       = make_float2(cf[0] + bx, cf[1] + by);
            *(float2*)(C + (size_t)(r + 8) * N + cc) = make_float2(cf[2] + bx, cf[3] + by);
        }
    }
}

// ---------------- sparse attention: one block per query row, one warp per head ----------------
__global__ __launch_bounds__(256) void sparse_attn() {
    int i = blockIdx.x;
    int h = threadIdx.x >> 5;
    int lane = threadIdx.x & 31;
    int cnt = g_cnt[i];
    if (cnt > MAXNB) cnt = MAXNB;

    __shared__ float sc[HEADS][MAXNB];
    __shared__ int   cols_s[MAXNB];
    __shared__ float wts_s[MAXNB];

    for (int t = threadIdx.x; t < cnt; t += 256) {
        cols_s[t] = g_cols[i * MAXNB + t];
        wts_s[t]  = g_wts[i * MAXNB + t];
    }
    __syncthreads();

    float2 qv = *(const float2*)(g_qkv + (size_t)i * D3 + h * HD + lane * 2);

    // scores: 4 neighbors per iteration -> 4 interleaved shfl-reduce chains
    for (int t0 = 0; t0 < cnt; t0 += 4) {
        float d[4] = {0.f, 0.f, 0.f, 0.f};
        #pragma unroll
        for (int u = 0; u < 4; u++) {
            int t = t0 + u;
            if (t < cnt) {
                int j = cols_s[t];
                float2 kv = *(const float2*)(g_qkv + (size_t)j * D3 + Dd + h * HD + lane * 2);
                d[u] = qv.x * kv.x + qv.y * kv.y;
            }
        }
        #pragma unroll
        for (int o = 16; o; o >>= 1) {
            d[0] += __shfl_xor_sync(0xffffffffu, d[0], o);
            d[1] += __shfl_xor_sync(0xffffffffu, d[1], o);
            d[2] += __shfl_xor_sync(0xffffffffu, d[2], o);
            d[3] += __shfl_xor_sync(0xffffffffu, d[3], o);
        }
        if (lane == 0) {
            #pragma unroll
            for (int u = 0; u < 4; u++)
                if (t0 + u < cnt) sc[h][t0 + u] = d[u] * 0.125f + wts_s[t0 + u];
        }
    }
    __syncwarp();

    float m = -1e30f;
    for (int t = lane; t < cnt; t += 32) m = fmaxf(m, sc[h][t]);
    #pragma unroll
    for (int o = 16; o; o >>= 1) m = fmaxf(m, __shfl_xor_sync(0xffffffffu, m, o));

    float s = 0.0f;
    for (int t = lane; t < cnt; t += 32) {
        float e = expf(sc[h][t] - m);
        sc[h][t] = e;
        s += e;
    }
    #pragma unroll
    for (int o = 16; o; o >>= 1) s += __shfl_xor_sync(0xffffffffu, s, o);
    float inv = 1.0f / s;
    __syncwarp();

    float2 acc = make_float2(0.0f, 0.0f);
    for (int t = 0; t < cnt; t++) {
        float p = sc[h][t] * inv;
        int j = cols_s[t];
        float2 vv = *(const float2*)(g_qkv + (size_t)j * D3 + 2 * Dd + h * HD + lane * 2);
        acc.x += p * vv.x;
        acc.y += p * vv.y;
    }
    float* op = g_attn + (size_t)i * Dd + h * HD + lane * 2;
    op[0] = acc.x;
    op[1] = acc.y;
}

// ---------------- add + LayerNorm ----------------
// MODE 0: g_h1 = LN(x_arg + g_tmp);  MODE 1: out_ext = LN(g_h1 + g_tmp)
template<int MODE>
__global__ __launch_bounds__(256) void add_ln(
    const float* __restrict__ a_in,
    const float* __restrict__ g, const float* __restrict__ be,
    float* __restrict__ out_ext)
{
    const float* a = (MODE == 0) ? a_in : (const float*)g_h1;
    const float* b = (const float*)g_tmp;
    float*       o = (MODE == 0) ? (float*)g_h1 : out_ext;

    int i = blockIdx.x;
    int t = threadIdx.x;
    int lane = t & 31, w = t >> 5;
    __shared__ float sh[8];

    float2 av = *(const float2*)(a + (size_t)i * Dd + t * 2);
    float2 bv = *(const float2*)(b + (size_t)i * Dd + t * 2);
    float yx = av.x + bv.x;
    float yy = av.y + bv.y;

    float s = yx + yy;
    #pragma unroll
    for (int oo = 16; oo; oo >>= 1) s += __shfl_xor_sync(0xffffffffu, s, oo);
    if (lane == 0) sh[w] = s;
    __syncthreads();
    if (t == 0) {
        float tot = 0;
        #pragma unroll
        for (int k = 0; k < 8; k++) tot += sh[k];
        sh[0] = tot;
    }
    __syncthreads();
    float mu = sh[0] * (1.0f / Dd);
    __syncthreads();

    float dx = yx - mu, dy = yy - mu;
    float qq = dx * dx + dy * dy;
    #pragma unroll
    for (int oo = 16; oo; oo >>= 1) qq += __shfl_xor_sync(0xffffffffu, qq, oo);
    if (lane == 0) sh[w] = qq;
    __syncthreads();
    if (t == 0) {
        float tot = 0;
        #pragma unroll
        for (int k = 0; k < 8; k++) tot += sh[k];
        sh[0] = tot;
    }
    __syncthreads();
    float var = sh[0] * (1.0f / Dd);
    float r = rsqrtf(var + 1e-5f);

    float2 gv  = *(const float2*)(g + t * 2);
    float2 bev = *(const float2*)(be + t * 2);
    float2 o2;
    o2.x = dx * r * gv.x + bev.x;
    o2.y = dy * r * gv.y + bev.y;
    *(float2*)(o + (size_t)i * Dd + t * 2) = o2;
}

// ---------------- launch ----------------
extern "C" void kernel_launch(void* const* d_in, const int* in_sizes, int n_in,
                              void* d_out, int out_size) {
    const float* x    = (const float*)d_in[0];
    const void*  ei   = d_in[1];
    const float* ew   = (const float*)d_in[2];
    const float* Wqkv = (const float*)d_in[3];
    const float* bqkv = (const float*)d_in[4];
    const float* Wo   = (const float*)d_in[5];
    const float* bo   = (const float*)d_in[6];
    const float* W1   = (const float*)d_in[7];
    const float* b1   = (const float*)d_in[8];
    const float* g1   = (const float*)d_in[9];
    const float* be1  = (const float*)d_in[10];
    const float* g2   = (const float*)d_in[11];
    const float* be2  = (const float*)d_in[12];
    float* out = (float*)d_out;

    // adjacency with exact last-write-wins dedup (winner grid self-restores to zero)
    k_scatter<<<Ee / 256, 256>>>(ei);
    k_append<<<Ee / 256, 256>>>(ei, ew);
    k_cleanup<<<Ee / 256, 256>>>(ei);

    // qkv = x @ Wqkv^T + bqkv            -> g_qkv
    tc_gemm<0><<<dim3(D3 / BN, Nn / BM), 128>>>(x, Wqkv, bqkv);

    // sparse multi-head attention        -> g_attn
    sparse_attn<<<Nn, 256>>>();

    // attn_out = g_attn @ Wo^T + bo      -> g_tmp
    tc_gemm<1><<<dim3(Dd / BN, Nn / BM), 128>>>(nullptr, Wo, bo);

    // h1 = LN(x + g_tmp)                 -> g_h1
    add_ln<0><<<Nn, 256>>>(x, g1, be1, out);

    // ffn = g_h1 @ W1^T + b1             -> g_tmp
    tc_gemm<2><<<dim3(Dd / BN, Nn / BM), 128>>>(nullptr, W1, b1);

    // out = LN(g_h1 + g_tmp)             -> out
    add_ln<1><<<Nn, 256>>>(nullptr, g2, be2, out);
}

// round 9
// speedup vs baseline: 1.0862x; 1.0010x over previous
#include <cuda_runtime.h>
#include <math.h>
#include <stdint.h>

#define Nn 4096
#define Dd 512
#define D3 1536
#define Ee 131072
#define MAXNB 128
#define HEADS 8
#define HD 64

// ---------------- scratch (device globals; referenced ONLY from device code) ----------------
__device__ int   g_winner[Nn * Nn];     // 0 = empty; else edge_id+1 (zero-init, self-restoring)
__device__ __align__(128) int   g_cnt[Nn];
__device__ __align__(128) int   g_cols[Nn * MAXNB];
__device__ __align__(128) float g_wts[Nn * MAXNB];
__device__ __align__(128) float g_qkv[Nn * D3];
__device__ __align__(128) float g_attn[Nn * Dd];
__device__ __align__(128) float g_tmp[Nn * Dd];
__device__ __align__(128) float g_h1[Nn * Dd];

// ---------------- helpers ----------------
__device__ __forceinline__ uint32_t smem_u32(const void* p) {
    uint32_t a;
    asm("{ .reg .u64 t; cvta.to.shared.u64 t, %1; cvt.u32.u64 %0, t; }" : "=r"(a) : "l"(p));
    return a;
}
__device__ __forceinline__ uint32_t f2tf(uint32_t fb) {
    uint32_t u;
    asm("cvt.rna.tf32.f32 %0, %1;" : "=r"(u) : "f"(__uint_as_float(fb)));
    return u;
}
__device__ __forceinline__ void cp16cg(uint32_t dst, const void* src) {
    asm volatile("cp.async.cg.shared.global [%0], [%1], 16;" :: "r"(dst), "l"(src));
}
__device__ __forceinline__ void ldsm4(uint32_t* r, uint32_t addr) {
    asm volatile("ldmatrix.sync.aligned.m8n8.x4.shared.b16 {%0,%1,%2,%3}, [%4];"
        : "=r"(r[0]), "=r"(r[1]), "=r"(r[2]), "=r"(r[3]) : "r"(addr));
}
__device__ __forceinline__ void mma8(float* c, const uint32_t* a, const uint32_t* b) {
    asm volatile(
        "mma.sync.aligned.m16n8k8.row.col.f32.tf32.tf32.f32 "
        "{%0,%1,%2,%3},{%4,%5,%6,%7},{%8,%9},{%0,%1,%2,%3};"
        : "+f"(c[0]), "+f"(c[1]), "+f"(c[2]), "+f"(c[3])
        : "r"(a[0]), "r"(a[1]), "r"(a[2]), "r"(a[3]), "r"(b[0]), "r"(b[1]));
}

// ---------------- edge access (dtype auto-detect per-thread) ----------------
__device__ __forceinline__ bool edge_is64(const void* ei) {
    const uint32_t* w = (const uint32_t*)ei;
    return (w[1] | w[3] | w[5] | w[7]) == 0u;
}
__device__ __forceinline__ int2 load_edge(const void* ei, int e, bool is64) {
    int2 r;
    if (is64) {
        const long long* p = (const long long*)ei;
        r.x = (int)p[e];
        r.y = (int)p[Ee + e];
    } else {
        const int* p = (const int*)ei;
        r.x = p[e];
        r.y = p[Ee + e];
    }
    return r;
}

// ---------------- adjacency build ----------------
__global__ void k_scatter(const void* __restrict__ ei) {
    int e = blockIdx.x * blockDim.x + threadIdx.x;
    if (e < Nn) g_cnt[e] = 0;
    if (e >= Ee) return;
    bool is64 = edge_is64(ei);
    int2 sd = load_edge(ei, e, is64);
    if ((unsigned)sd.x >= Nn || (unsigned)sd.y >= Nn) return;
    atomicMax(&g_winner[sd.y * Nn + sd.x], e + 1);
}

__global__ void k_append(const void* __restrict__ ei, const float* __restrict__ ew) {
    int e = blockIdx.x * blockDim.x + threadIdx.x;
    if (e < Nn && g_winner[e * Nn + e] == 0) {       // self edge (diag not overridden)
        int s = atomicAdd(&g_cnt[e], 1);
        if (s < MAXNB) { g_cols[e * MAXNB + s] = e; g_wts[e * MAXNB + s] = 0.0f; }
    }
    if (e >= Ee) return;
    bool is64 = edge_is64(ei);
    int2 sd = load_edge(ei, e, is64);
    if ((unsigned)sd.x >= Nn || (unsigned)sd.y >= Nn) return;
    if (g_winner[sd.y * Nn + sd.x] == e + 1) {       // surviving write for (dst,src)
        int s = atomicAdd(&g_cnt[sd.y], 1);
        if (s < MAXNB) { g_cols[sd.y * MAXNB + s] = sd.x; g_wts[sd.y * MAXNB + s] = ew[e]; }
    }
}

__global__ void k_cleanup(const void* __restrict__ ei) {
    int e = blockIdx.x * blockDim.x + threadIdx.x;
    if (e >= Ee) return;
    bool is64 = edge_is64(ei);
    int2 sd = load_edge(ei, e, is64);
    if ((unsigned)sd.x >= Nn || (unsigned)sd.y >= Nn) return;
    g_winner[sd.y * Nn + sd.x] = 0;                  // restore zero-state for next replay
}

// ---------------- tf32 mma GEMM: C[M,N] = A[M,K] * B[N,K]^T + bias[N] ----------------
// 128x128 CTA tile, 4 warps of 64x64, K-slab 16, cp.async.cg double-buffer, ldmatrix frags.
#define BM 128
#define BN 128
#define SLAB 16
#define NSLAB (Dd / SLAB)   // 32
#define SPAD 20             // row stride in floats: 80B (16B-aligned, ldmatrix conflict-free)

template<int MODE>
__global__ __launch_bounds__(128) void tc_gemm(
    const float* __restrict__ Ax,
    const float* __restrict__ Bw,
    const float* __restrict__ bias)
{
    constexpr int N = (MODE == 0) ? D3 : Dd;
    constexpr int K = Dd;
    const float* A = (MODE == 0) ? Ax : ((MODE == 1) ? (const float*)g_attn : (const float*)g_h1);
    float*       C = (MODE == 0) ? (float*)g_qkv : (float*)g_tmp;

    __shared__ __align__(16) float As[2][BM * SPAD];
    __shared__ __align__(16) float Bs[2][BN * SPAD];

    int tid  = threadIdx.x;
    int warp = tid >> 5;
    int lane = tid & 31;
    int g  = lane >> 2;
    int t4 = lane & 3;
    int wRow = (warp >> 1) * 64;
    int wCol = (warp & 1) * 64;

    int rowBase = blockIdx.y * BM;
    int colBase = blockIdx.x * BN;

    const float* Ag = A  + (size_t)(rowBase + tid) * K;   // one row per thread
    const float* Bg = Bw + (size_t)(colBase + tid) * K;
    uint32_t dA[2], dB[2];
    dA[0] = smem_u32(&As[0][tid * SPAD]);
    dA[1] = smem_u32(&As[1][tid * SPAD]);
    dB[0] = smem_u32(&Bs[0][tid * SPAD]);
    dB[1] = smem_u32(&Bs[1][tid * SPAD]);

    // ldmatrix lane-address bases (byte addresses into buffer 0)
    // A tile mt at k-step ks: addr = aBase + buf + (mt*16*SPAD + ks)*4
    //   row = wRow + (lane&15), col-quad = (lane>>4)*4
    uint32_t aBase = smem_u32(&As[0][0]) +
        4u * ((wRow + (lane & 15)) * SPAD + ((lane >> 4) & 1) * 4);
    // B pair p (tiles 2p,2p+1): row = wCol + (lane&7) + ((lane>>4)&1)*8, col-quad = ((lane>>3)&1)*4
    uint32_t bBase = smem_u32(&Bs[0][0]) +
        4u * ((wCol + (lane & 7) + ((lane >> 4) & 1) * 8) * SPAD + ((lane >> 3) & 1) * 4);
    const uint32_t ABUF = BM * SPAD * 4;
    const uint32_t BBUF = BN * SPAD * 4;

    float acc[4][8][4];
    #pragma unroll
    for (int mt = 0; mt < 4; mt++)
        #pragma unroll
        for (int nt = 0; nt < 8; nt++)
            #pragma unroll
            for (int j = 0; j < 4; j++) acc[mt][nt][j] = 0.0f;

    // prologue: stage slab 0 into buffer 0
    #pragma unroll
    for (int c = 0; c < 4; c++) {
        cp16cg(dA[0] + c * 16, Ag + c * 4);
        cp16cg(dB[0] + c * 16, Bg + c * 4);
    }
    asm volatile("cp.async.commit_group;" ::: "memory");

    for (int s = 0; s < NSLAB; s++) {
        int b = s & 1;
        if (s + 1 < NSLAB) {
            const float* a2 = Ag + (s + 1) * SLAB;
            const float* b2 = Bg + (s + 1) * SLAB;
            #pragma unroll
            for (int c = 0; c < 4; c++) {
                cp16cg(dA[b ^ 1] + c * 16, a2 + c * 4);
                cp16cg(dB[b ^ 1] + c * 16, b2 + c * 4);
            }
        }
        asm volatile("cp.async.commit_group;" ::: "memory");
        asm volatile("cp.async.wait_group 1;" ::: "memory");
        __syncthreads();

        uint32_t abuf = b ? ABUF : 0u;
        uint32_t bbuf = b ? BBUF : 0u;

        #pragma unroll
        for (int ks = 0; ks < SLAB; ks += 8) {
            uint32_t ua[4][4], ub[4][4];
            #pragma unroll
            for (int mt = 0; mt < 4; mt++)
                ldsm4(ua[mt], aBase + abuf + 4u * (mt * 16 * SPAD + ks));
            #pragma unroll
            for (int p = 0; p < 4; p++)
                ldsm4(ub[p], bBase + bbuf + 4u * (p * 16 * SPAD + ks));
            // convert fp32 bits -> tf32 (rna) in registers
            #pragma unroll
            for (int mt = 0; mt < 4; mt++)
                #pragma unroll
                for (int j = 0; j < 4; j++) ua[mt][j] = f2tf(ua[mt][j]);
            #pragma unroll
            for (int p = 0; p < 4; p++)
                #pragma unroll
                for (int j = 0; j < 4; j++) ub[p][j] = f2tf(ub[p][j]);

            #pragma unroll
            for (int mt = 0; mt < 4; mt++) {
                #pragma unroll
                for (int p = 0; p < 4; p++) {
                    mma8(acc[mt][2 * p],     ua[mt], &ub[p][0]);   // tile 2p   : regs 0,1
                    mma8(acc[mt][2 * p + 1], ua[mt], &ub[p][2]);   // tile 2p+1 : regs 2,3
                }
            }
        }
        __syncthreads();
    }

    // epilogue: c0,c1 -> (row g, col 2*t4..+1); c2,c3 -> row g+8
    #pragma unroll
    for (int mt = 0; mt < 4; mt++) {
        #pragma unroll
        for (int nt = 0; nt < 8; nt++) {
            float* cf = acc[mt][nt];
            int r  = rowBase + wRow + mt * 16 + g;
            int cc = colBase + wCol + nt * 8 + t4 * 2;
            float bx = bias[cc], by = bias[cc + 1];
            *(float2*)(C + (size_t)r * N + cc)       = make_float2(cf[0] + bx, cf[1] + by);
            *(float2*)(C + (size_t)(r + 8) * N + cc) = make_float2(cf[2] + bx, cf[3] + by);
        }
    }
}

// ---------------- sparse attention: one block per query row, one warp per head ----------------
__global__ __launch_bounds__(256) void sparse_attn() {
    int i = blockIdx.x;
    int h = threadIdx.x >> 5;
    int lane = threadIdx.x & 31;
    int cnt = g_cnt[i];
    if (cnt > MAXNB) cnt = MAXNB;

    __shared__ float sc[HEADS][MAXNB];
    __shared__ int   cols_s[MAXNB];
    __shared__ float wts_s[MAXNB];

    for (int t = threadIdx.x; t < cnt; t += 256) {
        cols_s[t] = g_cols[i * MAXNB + t];
        wts_s[t]  = g_wts[i * MAXNB + t];
    }
    __syncthreads();

    float2 qv = *(const float2*)(g_qkv + (size_t)i * D3 + h * HD + lane * 2);

    // scores: 4 neighbors per iteration -> 4 interleaved shfl-reduce chains
    for (int t0 = 0; t0 < cnt; t0 += 4) {
        float d[4] = {0.f, 0.f, 0.f, 0.f};
        #pragma unroll
        for (int u = 0; u < 4; u++) {
            int t = t0 + u;
            if (t < cnt) {
                int j = cols_s[t];
                float2 kv = *(const float2*)(g_qkv + (size_t)j * D3 + Dd + h * HD + lane * 2);
                d[u] = qv.x * kv.x + qv.y * kv.y;
            }
        }
        #pragma unroll
        for (int o = 16; o; o >>= 1) {
            d[0] += __shfl_xor_sync(0xffffffffu, d[0], o);
            d[1] += __shfl_xor_sync(0xffffffffu, d[1], o);
            d[2] += __shfl_xor_sync(0xffffffffu, d[2], o);
            d[3] += __shfl_xor_sync(0xffffffffu, d[3], o);
        }
        if (lane == 0) {
            #pragma unroll
            for (int u = 0; u < 4; u++)
                if (t0 + u < cnt) sc[h][t0 + u] = d[u] * 0.125f + wts_s[t0 + u];
        }
    }
    __syncwarp();

    float m = -1e30f;
    for (int t = lane; t < cnt; t += 32) m = fmaxf(m, sc[h][t]);
    #pragma unroll
    for (int o = 16; o; o >>= 1) m = fmaxf(m, __shfl_xor_sync(0xffffffffu, m, o));

    float s = 0.0f;
    for (int t = lane; t < cnt; t += 32) {
        float e = expf(sc[h][t] - m);
        sc[h][t] = e;
        s += e;
    }
    #pragma unroll
    for (int o = 16; o; o >>= 1) s += __shfl_xor_sync(0xffffffffu, s, o);
    float inv = 1.0f / s;
    __syncwarp();

    float2 acc = make_float2(0.0f, 0.0f);
    for (int t = 0; t < cnt; t++) {
        float p = sc[h][t] * inv;
        int j = cols_s[t];
        float2 vv = *(const float2*)(g_qkv + (size_t)j * D3 + 2 * Dd + h * HD + lane * 2);
        acc.x += p * vv.x;
        acc.y += p * vv.y;
    }
    float* op = g_attn + (size_t)i * Dd + h * HD + lane * 2;
    op[0] = acc.x;
    op[1] = acc.y;
}

// ---------------- add + LayerNorm ----------------
// MODE 0: g_h1 = LN(x_arg + g_tmp);  MODE 1: out_ext = LN(g_h1 + g_tmp)
template<int MODE>
__global__ __launch_bounds__(256) void add_ln(
    const float* __restrict__ a_in,
    const float* __restrict__ g, const float* __restrict__ be,
    float* __restrict__ out_ext)
{
    const float* a = (MODE == 0) ? a_in : (const float*)g_h1;
    const float* b = (const float*)g_tmp;
    float*       o = (MODE == 0) ? (float*)g_h1 : out_ext;

    int i = blockIdx.x;
    int t = threadIdx.x;
    int lane = t & 31, w = t >> 5;
    __shared__ float sh[8];

    float2 av = *(const float2*)(a + (size_t)i * Dd + t * 2);
    float2 bv = *(const float2*)(b + (size_t)i * Dd + t * 2);
    float yx = av.x + bv.x;
    float yy = av.y + bv.y;

    float s = yx + yy;
    #pragma unroll
    for (int oo = 16; oo; oo >>= 1) s += __shfl_xor_sync(0xffffffffu, s, oo);
    if (lane == 0) sh[w] = s;
    __syncthreads();
    if (t == 0) {
        float tot = 0;
        #pragma unroll
        for (int k = 0; k < 8; k++) tot += sh[k];
        sh[0] = tot;
    }
    __syncthreads();
    float mu = sh[0] * (1.0f / Dd);
    __syncthreads();

    float dx = yx - mu, dy = yy - mu;
    float qq = dx * dx + dy * dy;
    #pragma unroll
    for (int oo = 16; oo; oo >>= 1) qq += __shfl_xor_sync(0xffffffffu, qq, oo);
    if (lane == 0) sh[w] = qq;
    __syncthreads();
    if (t == 0) {
        float tot = 0;
        #pragma unroll
        for (int k = 0; k < 8; k++) tot += sh[k];
        sh[0] = tot;
    }
    __syncthreads();
    float var = sh[0] * (1.0f / Dd);
    float r = rsqrtf(var + 1e-5f);

    float2 gv  = *(const float2*)(g + t * 2);
    float2 bev = *(const float2*)(be + t * 2);
    float2 o2;
    o2.x = dx * r * gv.x + bev.x;
    o2.y = dy * r * gv.y + bev.y;
    *(float2*)(o + (size_t)i * Dd + t * 2) = o2;
}

// ---------------- launch ----------------
extern "C" void kernel_launch(void* const* d_in, const int* in_sizes, int n_in,
                              void* d_out, int out_size) {
    const float* x    = (const float*)d_in[0];
    const void*  ei   = d_in[1];
    const float* ew   = (const float*)d_in[2];
    const float* Wqkv = (const float*)d_in[3];
    const float* bqkv = (const float*)d_in[4];
    const float* Wo   = (const float*)d_in[5];
    const float* bo   = (const float*)d_in[6];
    const float* W1   = (const float*)d_in[7];
    const float* b1   = (const float*)d_in[8];
    const float* g1   = (const float*)d_in[9];
    const float* be1  = (const float*)d_in[10];
    const float* g2   = (const float*)d_in[11];
    const float* be2  = (const float*)d_in[12];
    float* out = (float*)d_out;

    // adjacency with exact last-write-wins dedup (winner grid self-restores to zero)
    k_scatter<<<Ee / 256, 256>>>(ei);
    k_append<<<Ee / 256, 256>>>(ei, ew);
    k_cleanup<<<Ee / 256, 256>>>(ei);

    // qkv = x @ Wqkv^T + bqkv            -> g_qkv
    tc_gemm<0><<<dim3(D3 / BN, Nn / BM), 128>>>(x, Wqkv, bqkv);

    // sparse multi-head attention        -> g_attn
    sparse_attn<<<Nn, 256>>>();

    // attn_out = g_attn @ Wo^T + bo      -> g_tmp
    tc_gemm<1><<<dim3(Dd / BN, Nn / BM), 128>>>(nullptr, Wo, bo);

    // h1 = LN(x + g_tmp)                 -> g_h1
    add_ln<0><<<Nn, 256>>>(x, g1, be1, out);

    // ffn = g_h1 @ W1^T + b1             -> g_tmp
    tc_gemm<2><<<dim3(Dd / BN, Nn / BM), 128>>>(nullptr, W1, b1);

    // out = LN(g_h1 + g_tmp)             -> out
    add_ln<1><<<Nn, 256>>>(nullptr, g2, be2, out);
}